// round 10
// baseline (speedup 1.0000x reference)
#include <cuda_runtime.h>
#include <math.h>

#define NMESH 2001
#define B 8
#define NP 1024
#define TSPLIT 16
#define TCHUNK 126            // TSPLIT * TCHUNK = 2016 >= NMESH
#define HB_BLOCKS 63          // 63 * 32 = 2016 >= NMESH
#define RHO_BLOCKS_PER_B 16

static constexpr double PI_D = 3.14159265358979323846;
static constexpr double TAU_D = 12.0 * (1.0 / (2.0 * PI_D * (double)NMESH)) * (1.0 / (2.0 * PI_D * (double)NMESH));
static constexpr float  TAU_F = (float)TAU_D;
static constexpr float  FOUR_PI_F = 12.566371f;     // np.float32(4*pi)
static constexpr float  SQRT_2PI_F = 2.5066283f;    // np.float32(sqrt(2*pi))
static constexpr double INV_N_D = 1.0 / (double)NMESH;

// scratch (device globals -- no allocation allowed)
__device__ float2 g_h[2048];                     // (h0[m], h1[m]) conv kernels (1/N^2 folded in)
__device__ float  g_rho[B][2048];                // gridded density
__device__ float  g_part[TSPLIT][B][2][2048];    // deterministic conv partials
__device__ float  g_conv[B][2][2048];            // rho (*) h_c

// ---------------------------------------------------------------------------
// K_prep: fused (hbuild || rho), role by blockIdx.x.
//
// hbuild role (blocks 0..62):
//   Recompute the real spectral multiplier table M~[q] (q=0..1000) in shared
//   (M~[q] = centered multiplier at k = 2*pi*q; fold the q==0?1:2 cosine
//   pairing and the 1/N^2 of ifft + /NMESH), then
//   h_c[m] = sum_q M~_c[q] * cos(2*pi*(q*m mod N)/N)
//   with an 8-way q-split per m (256 thr = 32 m x 8 slices) + shared reduce.
//
// rho role (blocks 63..190):
//   rho[b][n] = (1/(sqrt(2pi)*s)) * sum_p exp(-0.5*wrap(x_p-x_n)^2/s^2).
//   Single wrapped image is fp32-identical to the 3-image periodized sum
//   (far images underflow to exactly 0 for s ~ 0.02); d - rint(d) is exact
//   (Sterbenz) for d in (-1, 1).
// ---------------------------------------------------------------------------
__global__ void __launch_bounds__(256)
k_prep(const float* __restrict__ x,   const float* __restrict__ sv,
       const float* __restrict__ sh0, const float* __restrict__ sh1,
       const float* __restrict__ a0,  const float* __restrict__ a1) {
    __shared__ float sM0[1001], sM1[1001];
    __shared__ float sred0[256], sred1[256];
    __shared__ float xs[NP];

    int tid = threadIdx.x;

    if (blockIdx.x < HB_BLOCKS) {
        // ---- build multiplier table in shared ----
        float c0 = 5.0f * sh0[0];
        float c1 = 5.0f * sh1[0];
        float A0 = a0[0], A1 = a1[0];
        for (int q = tid; q <= 1000; q += 256) {
            float k  = (float)(2.0 * PI_D * (double)q);
            float k2 = k * k;
            float deconv = sqrtf((float)PI_D / TAU_F) * expf(k2 * TAU_F);
            float m1 = -A0 * FOUR_PI_F / (k2 + c0 * c0);
            float inv = 1.0f / (k2 + c1 * c1);
            float m2 = A1 * FOUR_PI_F * inv * inv;
            float scale = ((q == 0) ? 1.0f : 2.0f) * (float)(1.0 / ((double)NMESH * (double)NMESH));
            sM0[q] = m1 * deconv * scale;
            sM1[q] = m2 * deconv * scale;
        }
        __syncthreads();

        // ---- cosine transform ----
        int ml = tid & 31;           // m lane
        int qs = tid >> 5;           // q slice 0..7
        int m  = blockIdx.x * 32 + ml;
        const float step = (float)(2.0 * PI_D / (double)NMESH);
        float acc0 = 0.0f, acc1 = 0.0f;
        for (int i = 0; i < TCHUNK; i++) {
            int q = qs + (i << 3);
            if (q <= 1000) {
                int r  = (q * m) % NMESH;
                int rr = (r > 1000) ? (r - NMESH) : r;     // -> (-pi, pi]
                float w = __cosf((float)rr * step);
                acc0 = fmaf(sM0[q], w, acc0);
                acc1 = fmaf(sM1[q], w, acc1);
            }
        }
        sred0[tid] = acc0; sred1[tid] = acc1;
        __syncthreads();
#pragma unroll
        for (int off = 128; off >= 32; off >>= 1) {
            if (tid < off) { sred0[tid] += sred0[tid + off]; sred1[tid] += sred1[tid + off]; }
            __syncthreads();
        }
        if (tid < 32 && m < NMESH) g_h[m] = make_float2(sred0[tid], sred1[tid]);
    } else {
        // ---- gridding ----
        int rb   = blockIdx.x - HB_BLOCKS;           // 0..127
        int b    = rb >> 4;
        int nblk = rb & 15;
        for (int i = tid; i < NP; i += 256) xs[i] = x[b * NP + i];
        __syncthreads();

        int ml = tid & 127;
        int ph = tid >> 7;
        int n  = nblk * 128 + ml;
        float s = sv[0];
        float cexp = -0.5f / (s * s);
        float xn = (float)((double)n * INV_N_D);     // matches float32(XGRID) exactly
        float acc = 0.0f;
        int p0 = ph * 512;
#pragma unroll 4
        for (int p = p0; p < p0 + 512; p++) {
            float d = xs[p] - xn;
            d -= rintf(d);
            acc += __expf(cexp * d * d);
        }
        sred0[tid] = acc;
        __syncthreads();
        if (tid < 128) {
            float tot = sred0[tid] + sred0[tid + 128];
            if (n < NMESH) g_rho[b][n] = tot * (1.0f / (SQRT_2PI_F * s));
        }
    }
}

// ---------------------------------------------------------------------------
// K2: circular convolution, kernel-major form:
//   conv[b][c][n] = sum_t h_c[t] * rho[b][(n-t) mod N]
// h is broadcast (uniform) from shared; rho reads are per-lane consecutive
// (conflict-free). t-loop split TSPLIT ways across blocks; each block writes a
// deterministic partial. 4 outputs per thread (stride 256).
// ---------------------------------------------------------------------------
__global__ void __launch_bounds__(256)
k_conv() {
    __shared__ float  srho2[4049];       // rho[i mod N] for i in [0, 4049)
    __shared__ float2 shh[TCHUNK];
    int tid = threadIdx.x;
    int b   = blockIdx.y;
    int z   = blockIdx.z;
    int tlo = z * TCHUNK;
    int thi = min(tlo + TCHUNK, NMESH);

    for (int i = tid; i < 4049; i += 256) {
        int j = i;
        if (j >= 2 * NMESH) j -= 2 * NMESH;
        else if (j >= NMESH) j -= NMESH;
        srho2[i] = g_rho[b][j];
    }
    for (int i = tid; i < TCHUNK; i += 256) {
        int t = tlo + i;
        shh[i] = (t < NMESH) ? g_h[t] : make_float2(0.0f, 0.0f);
    }
    __syncthreads();

    int nb = blockIdx.x * 1024 + tid;    // base output index (j stride 256)
    float a00 = 0.f, a01 = 0.f, a10 = 0.f, a11 = 0.f, a20 = 0.f, a21 = 0.f, a30 = 0.f, a31 = 0.f;
#pragma unroll 2
    for (int t = tlo; t < thi; t++) {
        float2 hv = shh[t - tlo];
        int i0 = nb - t + NMESH;         // in [1, 4048] incl. +768
        float r0 = srho2[i0];
        float r1 = srho2[i0 + 256];
        float r2 = srho2[i0 + 512];
        float r3 = srho2[i0 + 768];
        a00 = fmaf(r0, hv.x, a00);  a01 = fmaf(r0, hv.y, a01);
        a10 = fmaf(r1, hv.x, a10);  a11 = fmaf(r1, hv.y, a11);
        a20 = fmaf(r2, hv.x, a20);  a21 = fmaf(r2, hv.y, a21);
        a30 = fmaf(r3, hv.x, a30);  a31 = fmaf(r3, hv.y, a31);
    }

    float acc0[4] = {a00, a10, a20, a30};
    float acc1[4] = {a01, a11, a21, a31};
#pragma unroll
    for (int j = 0; j < 4; j++) {
        int n = nb + j * 256;
        if (n < NMESH) {
            g_part[z][b][0][n] = acc0[j];
            g_part[z][b][1][n] = acc1[j];
        }
    }
}

// ---------------------------------------------------------------------------
// K2b: deterministic reduction of the TSPLIT partials (float4 vectorized).
// ---------------------------------------------------------------------------
__global__ void __launch_bounds__(256)
k_reduce() {
    int v = blockIdx.x * blockDim.x + threadIdx.x;     // over (B*2*2048)/4 float4s
    if (v >= (B * 2 * 2048) / 4) return;
    const float4* p = (const float4*)&g_part[0][0][0][0];
    float4 acc = make_float4(0.f, 0.f, 0.f, 0.f);
#pragma unroll
    for (int z = 0; z < TSPLIT; z++) {
        float4 t = p[z * ((B * 2 * 2048) / 4) + v];
        acc.x += t.x; acc.y += t.y; acc.z += t.z; acc.w += t.w;
    }
    ((float4*)&g_conv[0][0][0])[v] = acc;
}

// ---------------------------------------------------------------------------
// K3: resample at particle positions with the narrow gaussian window
// (support +-10 grid cells; weights beyond underflow to fp32 zero exactly as
// in the reference's full einsum). No periodic wrap (reference is unwrapped).
// ---------------------------------------------------------------------------
__global__ void __launch_bounds__(256)
k_resample(const float* __restrict__ x, float2* __restrict__ out) {
    int i = blockIdx.x * blockDim.x + threadIdx.x;
    if (i >= B * NP) return;
    int b = i >> 10;
    float xp = x[i];
    int n0 = __float2int_rn(xp * (float)NMESH);
    int lo = max(n0 - 10, 0);
    int hi = min(n0 + 10, NMESH - 1);
    const float cg = -1.0f / (4.0f * TAU_F);
    float acc0 = 0.0f, acc1 = 0.0f;
    for (int n = lo; n <= hi; n++) {
        float xn = (float)((double)n * INV_N_D);   // matches float32(XGRID)
        float d = xp - xn;
        float w = __expf(cg * d * d);
        acc0 = fmaf(w, g_conv[b][0][n], acc0);
        acc1 = fmaf(w, g_conv[b][1][n], acc1);
    }
    out[i] = make_float2(acc0, acc1);
}

// ---------------------------------------------------------------------------
extern "C" void kernel_launch(void* const* d_in, const int* in_sizes, int n_in,
                              void* d_out, int out_size) {
    const float* x   = (const float*)d_in[0];
    const float* sv  = (const float*)d_in[1];
    const float* sh0 = (const float*)d_in[2];
    const float* sh1 = (const float*)d_in[3];
    const float* a0  = (const float*)d_in[4];
    const float* a1  = (const float*)d_in[5];
    float2* out = (float2*)d_out;

    k_prep<<<HB_BLOCKS + RHO_BLOCKS_PER_B * B, 256>>>(x, sv, sh0, sh1, a0, a1);
    k_conv<<<dim3(2, B, TSPLIT), 256>>>();
    k_reduce<<<(B * 2 * 2048 / 4 + 255) / 256, 256>>>();
    k_resample<<<(B * NP + 255) / 256, 256>>>(x, out);
}

// round 13
// speedup vs baseline: 1.0476x; 1.0476x over previous
#include <cuda_runtime.h>
#include <math.h>

#define NMESH 2001
#define B 8
#define NP 1024
#define TSPLIT 16
#define TCHUNK 126            // TSPLIT * TCHUNK = 2016 >= NMESH
#define HB_BLOCKS 63          // 63 * 32 = 2016 >= NMESH
#define RHO_BLOCKS_PER_B 16

static constexpr double PI_D = 3.14159265358979323846;
static constexpr double TAU_D = 12.0 * (1.0 / (2.0 * PI_D * (double)NMESH)) * (1.0 / (2.0 * PI_D * (double)NMESH));
static constexpr float  TAU_F = (float)TAU_D;
static constexpr float  FOUR_PI_F = 12.566371f;     // np.float32(4*pi)
static constexpr float  SQRT_2PI_F = 2.5066283f;    // np.float32(sqrt(2*pi))
static constexpr double INV_N_D = 1.0 / (double)NMESH;

// scratch (device globals -- no allocation allowed)
__device__ float2 g_h[2048];                     // (h0[m], h1[m]) conv kernels (1/N^2 folded in)
__device__ float  g_rho[B][2048];                // gridded density
__device__ float  g_part[TSPLIT][B][2][2048];    // deterministic conv partials
__device__ float2 g_convi[B][2048];              // rho (*) h_c, channel-interleaved

// ---------------------------------------------------------------------------
// K_prep: fused (hbuild || rho), role by blockIdx.x.
//
// hbuild role (blocks 0..62):
//   Recompute the real spectral multiplier table M~[q] (q=0..1000) in shared
//   (fold the q==0?1:2 cosine pairing and the 1/N^2 of ifft + /NMESH), then
//   h_c[m] = sum_q M~_c[q] * cos(2*pi*(q*m mod N)/N)
//   with an 8-way q-split per m (256 thr = 32 m x 8 slices) + shared reduce.
//
// rho role (blocks 63..190):
//   rho[b][n] = (1/(sqrt(2pi)*s)) * sum_p exp(-0.5*wrap(x_p-x_n)^2/s^2).
//   Single wrapped image is fp32-identical to the 3-image periodized sum
//   (far images underflow to exactly 0 for s ~ 0.02); d - rint(d) is exact
//   (Sterbenz) for d in (-1, 1).
// ---------------------------------------------------------------------------
__global__ void __launch_bounds__(256)
k_prep(const float* __restrict__ x,   const float* __restrict__ sv,
       const float* __restrict__ sh0, const float* __restrict__ sh1,
       const float* __restrict__ a0,  const float* __restrict__ a1) {
    __shared__ float sM0[1001], sM1[1001];
    __shared__ float sred0[256], sred1[256];
    __shared__ float xs[NP];

    int tid = threadIdx.x;

    if (blockIdx.x < HB_BLOCKS) {
        // ---- build multiplier table in shared ----
        float c0 = 5.0f * sh0[0];
        float c1 = 5.0f * sh1[0];
        float A0 = a0[0], A1 = a1[0];
        for (int q = tid; q <= 1000; q += 256) {
            float k  = (float)(2.0 * PI_D * (double)q);
            float k2 = k * k;
            float deconv = sqrtf((float)PI_D / TAU_F) * expf(k2 * TAU_F);
            float m1 = -A0 * FOUR_PI_F / (k2 + c0 * c0);
            float inv = 1.0f / (k2 + c1 * c1);
            float m2 = A1 * FOUR_PI_F * inv * inv;
            float scale = ((q == 0) ? 1.0f : 2.0f) * (float)(1.0 / ((double)NMESH * (double)NMESH));
            sM0[q] = m1 * deconv * scale;
            sM1[q] = m2 * deconv * scale;
        }
        __syncthreads();

        // ---- cosine transform ----
        int ml = tid & 31;           // m lane
        int qs = tid >> 5;           // q slice 0..7
        int m  = blockIdx.x * 32 + ml;
        const float step = (float)(2.0 * PI_D / (double)NMESH);
        float acc0 = 0.0f, acc1 = 0.0f;
        for (int i = 0; i < TCHUNK; i++) {
            int q = qs + (i << 3);
            if (q <= 1000) {
                int r  = (q * m) % NMESH;
                int rr = (r > 1000) ? (r - NMESH) : r;     // -> (-pi, pi]
                float w = __cosf((float)rr * step);
                acc0 = fmaf(sM0[q], w, acc0);
                acc1 = fmaf(sM1[q], w, acc1);
            }
        }
        sred0[tid] = acc0; sred1[tid] = acc1;
        __syncthreads();
#pragma unroll
        for (int off = 128; off >= 32; off >>= 1) {
            if (tid < off) { sred0[tid] += sred0[tid + off]; sred1[tid] += sred1[tid + off]; }
            __syncthreads();
        }
        if (tid < 32 && m < NMESH) g_h[m] = make_float2(sred0[tid], sred1[tid]);
    } else {
        // ---- gridding ----
        int rb   = blockIdx.x - HB_BLOCKS;           // 0..127
        int b    = rb >> 4;
        int nblk = rb & 15;
        for (int i = tid; i < NP; i += 256) xs[i] = x[b * NP + i];
        __syncthreads();

        int ml = tid & 127;
        int ph = tid >> 7;
        int n  = nblk * 128 + ml;
        float s = sv[0];
        float cexp = -0.5f / (s * s);
        float xn = (float)((double)n * INV_N_D);     // matches float32(XGRID) exactly
        float acc = 0.0f;
        int p0 = ph * 512;
#pragma unroll 4
        for (int p = p0; p < p0 + 512; p++) {
            float d = xs[p] - xn;
            d -= rintf(d);
            acc += __expf(cexp * d * d);
        }
        sred0[tid] = acc;
        __syncthreads();
        if (tid < 128) {
            float tot = sred0[tid] + sred0[tid + 128];
            if (n < NMESH) g_rho[b][n] = tot * (1.0f / (SQRT_2PI_F * s));
        }
    }
}

// ---------------------------------------------------------------------------
// K2: circular convolution, kernel-major form:
//   conv[b][c][n] = sum_t h_c[t] * rho[b][(n-t) mod N]
// h is broadcast (uniform) from shared; rho reads are per-lane consecutive
// (conflict-free). t-loop split TSPLIT ways across blocks; each block writes a
// deterministic partial. 4 outputs per thread (stride 256).
// ---------------------------------------------------------------------------
__global__ void __launch_bounds__(256)
k_conv() {
    __shared__ float  srho2[4049];       // rho[i mod N] for i in [0, 4049)
    __shared__ float2 shh[TCHUNK];
    int tid = threadIdx.x;
    int b   = blockIdx.y;
    int z   = blockIdx.z;
    int tlo = z * TCHUNK;
    int thi = min(tlo + TCHUNK, NMESH);

    for (int i = tid; i < 4049; i += 256) {
        int j = i;
        if (j >= 2 * NMESH) j -= 2 * NMESH;
        else if (j >= NMESH) j -= NMESH;
        srho2[i] = g_rho[b][j];
    }
    for (int i = tid; i < TCHUNK; i += 256) {
        int t = tlo + i;
        shh[i] = (t < NMESH) ? g_h[t] : make_float2(0.0f, 0.0f);
    }
    __syncthreads();

    int nb = blockIdx.x * 1024 + tid;    // base output index (j stride 256)
    float a00 = 0.f, a01 = 0.f, a10 = 0.f, a11 = 0.f, a20 = 0.f, a21 = 0.f, a30 = 0.f, a31 = 0.f;
#pragma unroll 2
    for (int t = tlo; t < thi; t++) {
        float2 hv = shh[t - tlo];
        int i0 = nb - t + NMESH;         // in [1, 4048] incl. +768
        float r0 = srho2[i0];
        float r1 = srho2[i0 + 256];
        float r2 = srho2[i0 + 512];
        float r3 = srho2[i0 + 768];
        a00 = fmaf(r0, hv.x, a00);  a01 = fmaf(r0, hv.y, a01);
        a10 = fmaf(r1, hv.x, a10);  a11 = fmaf(r1, hv.y, a11);
        a20 = fmaf(r2, hv.x, a20);  a21 = fmaf(r2, hv.y, a21);
        a30 = fmaf(r3, hv.x, a30);  a31 = fmaf(r3, hv.y, a31);
    }

    float acc0[4] = {a00, a10, a20, a30};
    float acc1[4] = {a01, a11, a21, a31};
#pragma unroll
    for (int j = 0; j < 4; j++) {
        int n = nb + j * 256;
        if (n < NMESH) {
            g_part[z][b][0][n] = acc0[j];
            g_part[z][b][1][n] = acc1[j];
        }
    }
}

// ---------------------------------------------------------------------------
// K2b: deterministic reduction of the TSPLIT partials, writing the
// channel-interleaved conv buffer (one float2 per (b, n)). Same z-ascending
// summation order as before. 32 independent scalar loads per thread -> MLP 32.
// ---------------------------------------------------------------------------
__global__ void __launch_bounds__(256)
k_reduce() {
    int idx = blockIdx.x * blockDim.x + threadIdx.x;   // over B*2048
    if (idx >= B * 2048) return;
    int b = idx >> 11;
    int n = idx & 2047;
    float a0 = 0.0f, a1 = 0.0f;
#pragma unroll
    for (int z = 0; z < TSPLIT; z++) {
        a0 += g_part[z][b][0][n];
        a1 += g_part[z][b][1][n];
    }
    g_convi[b][n] = make_float2(a0, a1);
}

// ---------------------------------------------------------------------------
// K3: resample at particle positions with the narrow gaussian window.
// FIXED 21-iteration unrolled window (ptxas front-batches all 21 LDG.64 ->
// MLP ~21, latency paid once instead of serially; this was 9.3us at MLP~1).
// Out-of-range cells: address clamped for safety, weight zeroed by predicate
// -- identical math to the variable-bound loop / reference's full einsum.
// ---------------------------------------------------------------------------
__global__ void __launch_bounds__(128)
k_resample(const float* __restrict__ x, float2* __restrict__ out) {
    int i = blockIdx.x * blockDim.x + threadIdx.x;
    if (i >= B * NP) return;
    int b = i >> 10;
    float xp = x[i];
    int n0 = __float2int_rn(xp * (float)NMESH);
    const float cg = -1.0f / (4.0f * TAU_F);
    const float2* __restrict__ row = g_convi[b];
    float acc0 = 0.0f, acc1 = 0.0f;
#pragma unroll
    for (int j = 0; j < 21; j++) {
        int n  = n0 - 10 + j;
        int nc = min(max(n, 0), NMESH - 1);
        float2 cv = row[nc];
        float xn = (float)((double)n * INV_N_D);   // matches float32(XGRID)
        float d = xp - xn;
        float w = __expf(cg * d * d);
        w = (n == nc) ? w : 0.0f;                  // kill out-of-range cells
        acc0 = fmaf(w, cv.x, acc0);
        acc1 = fmaf(w, cv.y, acc1);
    }
    out[i] = make_float2(acc0, acc1);
}

// ---------------------------------------------------------------------------
extern "C" void kernel_launch(void* const* d_in, const int* in_sizes, int n_in,
                              void* d_out, int out_size) {
    const float* x   = (const float*)d_in[0];
    const float* sv  = (const float*)d_in[1];
    const float* sh0 = (const float*)d_in[2];
    const float* sh1 = (const float*)d_in[3];
    const float* a0  = (const float*)d_in[4];
    const float* a1  = (const float*)d_in[5];
    float2* out = (float2*)d_out;

    k_prep<<<HB_BLOCKS + RHO_BLOCKS_PER_B * B, 256>>>(x, sv, sh0, sh1, a0, a1);
    k_conv<<<dim3(2, B, TSPLIT), 256>>>();
    k_reduce<<<(B * 2048 + 255) / 256, 256>>>();
    k_resample<<<(B * NP + 127) / 128, 128>>>(x, out);
}